// round 14
// baseline (speedup 1.0000x reference)
#include <cuda_runtime.h>
#include <cuda_fp16.h>
#include <math.h>

#define NN 100000
#define EE 1600000
#define SCAN_B 1024
#define NBLK ((NN + SCAN_B - 1) / SCAN_B)   // 98

// ---------------- scratch (no allocations allowed) ----------------
__device__ __align__(16) float  g_dinv[NN];
__device__ __align__(16) int    g_degi[NN];
__device__ __align__(16) int    g_rowstart[NN + 1];
__device__ __align__(16) int    g_cursor[NN];
__device__ __align__(16) int    g_bsum[256];
__device__ __align__(16) int    g_bsum2[256];
__device__ __align__(16) int    g_esrc[EE];
__device__ __align__(16) __half g_xw_h[(size_t)NN * 128]; // x @ W1 (fp16)
__device__ __align__(16) float  g_h[(size_t)NN * 128];    // relu(agg layer1) fp32
__device__ __align__(16) __half g_hw2h[(size_t)NN * 40];  // h @ W2 (fp16)

// ---------------- degree histogram ----------------
__global__ void k_zero_deg() {
    int i = blockIdx.x * blockDim.x + threadIdx.x;
    if (i < NN) g_degi[i] = 0;
}

__global__ void k_hist(const int* __restrict__ ei) {
    int e = blockIdx.x * blockDim.x + threadIdx.x;
    if (e < EE) atomicAdd(&g_degi[ei[EE + e]], 1);
}

// ---------------- prefix scan (exclusive) of g_degi -> g_rowstart; fused dinv ----------------
__global__ void k_scan1() {
    __shared__ int sh[SCAN_B];
    int i = blockIdx.x * SCAN_B + threadIdx.x;
    int v = (i < NN) ? g_degi[i] : 0;
    if (i < NN) g_dinv[i] = rsqrtf((float)(v + 1));   // fused: deg + self loop
    sh[threadIdx.x] = v;
    __syncthreads();
    for (int o = 1; o < SCAN_B; o <<= 1) {
        int t = (threadIdx.x >= o) ? sh[threadIdx.x - o] : 0;
        __syncthreads();
        sh[threadIdx.x] += t;
        __syncthreads();
    }
    if (threadIdx.x == SCAN_B - 1) g_bsum[blockIdx.x] = sh[SCAN_B - 1];
    if (i < NN) g_rowstart[i] = sh[threadIdx.x] - v;   // exclusive
}

__global__ void k_scan2() {
    __shared__ int sh[128];
    int v = (threadIdx.x < NBLK) ? g_bsum[threadIdx.x] : 0;
    sh[threadIdx.x] = v;
    __syncthreads();
    for (int o = 1; o < 128; o <<= 1) {
        int t = (threadIdx.x >= o) ? sh[threadIdx.x - o] : 0;
        __syncthreads();
        sh[threadIdx.x] += t;
        __syncthreads();
    }
    g_bsum2[threadIdx.x] = sh[threadIdx.x] - v;        // exclusive
}

__global__ void k_scan3() {
    int i = blockIdx.x * blockDim.x + threadIdx.x;
    if (i < NN) {
        int r = g_rowstart[i] + g_bsum2[i / SCAN_B];
        g_rowstart[i] = r;
        g_cursor[i] = r;
    }
    if (i == 0) g_rowstart[NN] = EE;
}

// ---------------- counting-sort fill: CSR over dst ----------------
__global__ void k_fill(const int* __restrict__ ei) {
    int e = blockIdx.x * blockDim.x + threadIdx.x;
    if (e < EE) {
        int s = ei[e];
        int d = ei[EE + e];
        int pos = atomicAdd(&g_cursor[d], 1);
        g_esrc[pos] = s;
    }
}

// ---------------- mma + cp.async helpers ----------------
__device__ __forceinline__ void mma_tf32(float* d, const unsigned* a, const unsigned* b) {
    asm volatile(
        "mma.sync.aligned.m16n8k8.row.col.f32.tf32.tf32.f32 "
        "{%0,%1,%2,%3}, {%4,%5,%6,%7}, {%8,%9}, {%0,%1,%2,%3};"
        : "+f"(d[0]), "+f"(d[1]), "+f"(d[2]), "+f"(d[3])
        : "r"(a[0]), "r"(a[1]), "r"(a[2]), "r"(a[3]),
          "r"(b[0]), "r"(b[1]));
}

__device__ __forceinline__ void cp16(void* dst, const void* src, int src_bytes) {
    unsigned d = (unsigned)__cvta_generic_to_shared(dst);
    asm volatile("cp.async.cg.shared.global [%0], [%1], 16, %2;"
                 :: "r"(d), "l"(src), "r"(src_bytes) : "memory");
}
__device__ __forceinline__ void cp_commit() { asm volatile("cp.async.commit_group;" ::: "memory"); }
__device__ __forceinline__ void cp_wait1()  { asm volatile("cp.async.wait_group 1;" ::: "memory"); }
__device__ __forceinline__ void cp_wait0()  { asm volatile("cp.async.wait_group 0;" ::: "memory"); }

// ---------------- GEMM1 (tf32, 2-stage cp.async, 3 CTAs/SM forced) ----------------
// g_xw_h = fp16( x[N,256] @ W1[256,128] ). 128x128 block, 8 warps (2Mx4N), BK=16.
__global__ void __launch_bounds__(256, 3) k_gemm1(const float* __restrict__ A,
                                                  const float* __restrict__ B) {
    __shared__ float As[2][128][20];   // [m][k], stride 20 -> conflict-free frags
    __shared__ float Bs[2][16][132];   // [k][n]
    const int tid   = threadIdx.x;
    const int lane  = tid & 31;
    const int gid   = lane >> 2;    // 0..7
    const int tig   = lane & 3;     // 0..3
    const int warpM = (tid >> 5) & 1;
    const int warpN = (tid >> 6);   // 0..3
    const int blockRow = blockIdx.x * 128;

    float acc[4][4][4];
#pragma unroll
    for (int mt = 0; mt < 4; mt++)
#pragma unroll
        for (int nt = 0; nt < 4; nt++)
#pragma unroll
            for (int r = 0; r < 4; r++) acc[mt][nt][r] = 0.f;

    const int ar0 = tid >> 1, ak0 = (tid & 1) * 8;
    const int bk0 = tid >> 4, bn0 = (tid & 15) * 8;

    auto load_stage = [&](int st, int k0) {
        int row = blockRow + ar0;
        int ok  = (row < NN) ? 16 : 0;
        const float* src = &A[(size_t)row * 256 + k0 + ak0];
        cp16(&As[st][ar0][ak0],     src,     ok);
        cp16(&As[st][ar0][ak0 + 4], src + 4, ok);
        const float* bs = &B[(size_t)(k0 + bk0) * 128 + bn0];
        cp16(&Bs[st][bk0][bn0],     bs,     16);
        cp16(&Bs[st][bk0][bn0 + 4], bs + 4, 16);
        cp_commit();
    };

    load_stage(0, 0);

    for (int it = 0; it < 16; it++) {
        int st = it & 1;
        if (it + 1 < 16) {
            load_stage(st ^ 1, (it + 1) * 16);
            cp_wait1();
        } else {
            cp_wait0();
        }
        __syncthreads();

#pragma unroll
        for (int ks = 0; ks < 2; ks++) {
            int k = ks * 8 + tig;
            unsigned a[4][4], b[4][2];
#pragma unroll
            for (int mt = 0; mt < 4; mt++) {
                int r = warpM * 64 + mt * 16 + gid;
                a[mt][0] = __float_as_uint(As[st][r][k]);
                a[mt][1] = __float_as_uint(As[st][r + 8][k]);
                a[mt][2] = __float_as_uint(As[st][r][k + 4]);
                a[mt][3] = __float_as_uint(As[st][r + 8][k + 4]);
            }
#pragma unroll
            for (int nt = 0; nt < 4; nt++) {
                int c = warpN * 32 + nt * 8 + gid;
                b[nt][0] = __float_as_uint(Bs[st][k][c]);
                b[nt][1] = __float_as_uint(Bs[st][k + 4][c]);
            }
#pragma unroll
            for (int mt = 0; mt < 4; mt++)
#pragma unroll
                for (int nt = 0; nt < 4; nt++)
                    mma_tf32(acc[mt][nt], a[mt], b[nt]);
        }
        __syncthreads();
    }

#pragma unroll
    for (int mt = 0; mt < 4; mt++) {
        int r0 = blockRow + warpM * 64 + mt * 16 + gid;
#pragma unroll
        for (int nt = 0; nt < 4; nt++) {
            int c = warpN * 32 + nt * 8 + tig * 2;
            if (r0 < NN)
                *(__half2*)&g_xw_h[(size_t)r0 * 128 + c] =
                    __floats2half2_rn(acc[mt][nt][0], acc[mt][nt][1]);
            if (r0 + 8 < NN)
                *(__half2*)&g_xw_h[(size_t)(r0 + 8) * 128 + c] =
                    __floats2half2_rn(acc[mt][nt][2], acc[mt][nt][3]);
        }
    }
}

// ---------------- aggregation layer 1: warp per node, fp16 gather, 2-edge ILP ----------------
__global__ void __launch_bounds__(256) k_agg1(const float* __restrict__ b1) {
    int node = blockIdx.x * 8 + (threadIdx.x >> 5);
    int lane = threadIdx.x & 31;
    if (node >= NN) return;
    int beg = g_rowstart[node];
    int end = g_rowstart[node + 1];
    float dd = g_dinv[node];

    float4 acc = make_float4(0.f, 0.f, 0.f, 0.f);
    int i = beg;
    for (; i + 1 < end; i += 2) {
        int s0 = g_esrc[i];
        int s1 = g_esrc[i + 1];
        float n0 = dd * g_dinv[s0];
        float n1 = dd * g_dinv[s1];
        __half2 p0[2], p1[2];
        *(uint2*)p0 = *(const uint2*)&g_xw_h[(size_t)s0 * 128 + lane * 4];
        *(uint2*)p1 = *(const uint2*)&g_xw_h[(size_t)s1 * 128 + lane * 4];
        float2 a0 = __half22float2(p0[0]), a1 = __half22float2(p0[1]);
        float2 c0 = __half22float2(p1[0]), c1 = __half22float2(p1[1]);
        acc.x += a0.x * n0 + c0.x * n1;
        acc.y += a0.y * n0 + c0.y * n1;
        acc.z += a1.x * n0 + c1.x * n1;
        acc.w += a1.y * n0 + c1.y * n1;
    }
    if (i < end) {
        int s = g_esrc[i];
        float nrm = dd * g_dinv[s];
        __half2 p[2];
        *(uint2*)p = *(const uint2*)&g_xw_h[(size_t)s * 128 + lane * 4];
        float2 f0 = __half22float2(p[0]);
        float2 f1 = __half22float2(p[1]);
        acc.x += f0.x * nrm; acc.y += f0.y * nrm;
        acc.z += f1.x * nrm; acc.w += f1.y * nrm;
    }
    float self = dd * dd;
    __half2 sp[2];
    *(uint2*)sp = *(const uint2*)&g_xw_h[(size_t)node * 128 + lane * 4];
    float2 s0 = __half22float2(sp[0]);
    float2 s1 = __half22float2(sp[1]);
    float4 bb = *(const float4*)&b1[lane * 4];
    acc.x = fmaxf(acc.x + s0.x * self + bb.x, 0.f);
    acc.y = fmaxf(acc.y + s0.y * self + bb.y, 0.f);
    acc.z = fmaxf(acc.z + s1.x * self + bb.z, 0.f);
    acc.w = fmaxf(acc.w + s1.y * self + bb.w, 0.f);
    *(float4*)&g_h[(size_t)node * 128 + lane * 4] = acc;
}

// ---------------- GEMM2 (tf32 MMA, double-buffered; fp16 epilogue) ----------------
// 128-row block, 4 warps, warp tile 32x40 (2 x m16, 5 x n8), BK=32.
__global__ void __launch_bounds__(128) k_gemm2(const float* __restrict__ B) {
    __shared__ float As[2][128][36];   // [m][k] pad 4
    __shared__ float Bs[2][32][40];    // [k][n]
    const int tid  = threadIdx.x;
    const int lane = tid & 31;
    const int gid  = lane >> 2;
    const int tig  = lane & 3;
    const int warp = tid >> 5;         // 0..3
    const int blockRow = blockIdx.x * 128;

    float acc[2][5][4];
#pragma unroll
    for (int mt = 0; mt < 2; mt++)
#pragma unroll
        for (int nt = 0; nt < 5; nt++)
#pragma unroll
            for (int r = 0; r < 4; r++) acc[mt][nt][r] = 0.f;

    auto load_stage = [&](int st, int k0) {
        int row = blockRow + tid;
        int ok  = (row < NN) ? 16 : 0;
        const float* src = &g_h[(size_t)row * 128 + k0];
#pragma unroll
        for (int c = 0; c < 8; c++)
            cp16(&As[st][tid][c * 4], src + c * 4, ok);
#pragma unroll
        for (int idx = tid; idx < 320; idx += 128) {
            int kk = idx / 10;
            int c4 = (idx % 10) * 4;
            cp16(&Bs[st][kk][c4], &B[(size_t)(k0 + kk) * 40 + c4], 16);
        }
        cp_commit();
    };

    load_stage(0, 0);

    for (int it = 0; it < 4; it++) {
        int st = it & 1;
        if (it + 1 < 4) {
            load_stage(st ^ 1, (it + 1) * 32);
            cp_wait1();
        } else {
            cp_wait0();
        }
        __syncthreads();

#pragma unroll
        for (int ks = 0; ks < 4; ks++) {
            int k = ks * 8 + tig;
            unsigned a[2][4], b[5][2];
#pragma unroll
            for (int mt = 0; mt < 2; mt++) {
                int r = warp * 32 + mt * 16 + gid;
                a[mt][0] = __float_as_uint(As[st][r][k]);
                a[mt][1] = __float_as_uint(As[st][r + 8][k]);
                a[mt][2] = __float_as_uint(As[st][r][k + 4]);
                a[mt][3] = __float_as_uint(As[st][r + 8][k + 4]);
            }
#pragma unroll
            for (int nt = 0; nt < 5; nt++) {
                int c = nt * 8 + gid;
                b[nt][0] = __float_as_uint(Bs[st][k][c]);
                b[nt][1] = __float_as_uint(Bs[st][k + 4][c]);
            }
#pragma unroll
            for (int mt = 0; mt < 2; mt++)
#pragma unroll
                for (int nt = 0; nt < 5; nt++)
                    mma_tf32(acc[mt][nt], a[mt], b[nt]);
        }
        __syncthreads();
    }

#pragma unroll
    for (int mt = 0; mt < 2; mt++) {
        int r0 = blockRow + warp * 32 + mt * 16 + gid;
#pragma unroll
        for (int nt = 0; nt < 5; nt++) {
            int c = nt * 8 + tig * 2;
            if (r0 < NN)
                *(__half2*)&g_hw2h[(size_t)r0 * 40 + c] =
                    __floats2half2_rn(acc[mt][nt][0], acc[mt][nt][1]);
            if (r0 + 8 < NN)
                *(__half2*)&g_hw2h[(size_t)(r0 + 8) * 40 + c] =
                    __floats2half2_rn(acc[mt][nt][2], acc[mt][nt][3]);
        }
    }
}

// ---------------- aggregation layer 2 + bias + log_softmax, warp per node, fp16 gather ----------------
__global__ void __launch_bounds__(256) k_agg2(const float* __restrict__ b2,
                                              float* __restrict__ out) {
    int node = blockIdx.x * 8 + (threadIdx.x >> 5);
    int lane = threadIdx.x & 31;
    if (node >= NN) return;
    int beg = g_rowstart[node];
    int end = g_rowstart[node + 1];
    float dd = g_dinv[node];
    bool active = lane < 10;   // 10 x 4 halves cover 40 cols

    float4 acc = make_float4(0.f, 0.f, 0.f, 0.f);
    for (int i = beg; i < end; i++) {
        int s = g_esrc[i];
        float nrm = dd * g_dinv[s];
        if (active) {
            __half2 p[2];
            *(uint2*)p = *(const uint2*)&g_hw2h[(size_t)s * 40 + lane * 4];
            float2 f0 = __half22float2(p[0]);
            float2 f1 = __half22float2(p[1]);
            acc.x += f0.x * nrm; acc.y += f0.y * nrm;
            acc.z += f1.x * nrm; acc.w += f1.y * nrm;
        }
    }
    if (active) {
        float self = dd * dd;
        __half2 sp[2];
        *(uint2*)sp = *(const uint2*)&g_hw2h[(size_t)node * 40 + lane * 4];
        float2 s0 = __half22float2(sp[0]);
        float2 s1 = __half22float2(sp[1]);
        float4 bb = *(const float4*)&b2[lane * 4];
        acc.x += s0.x * self + bb.x;
        acc.y += s0.y * self + bb.y;
        acc.z += s1.x * self + bb.z;
        acc.w += s1.y * self + bb.w;
    }

    float m = active ? fmaxf(fmaxf(acc.x, acc.y), fmaxf(acc.z, acc.w)) : -INFINITY;
#pragma unroll
    for (int o = 16; o > 0; o >>= 1) m = fmaxf(m, __shfl_xor_sync(0xffffffffu, m, o));
    float s = active ? (expf(acc.x - m) + expf(acc.y - m) +
                        expf(acc.z - m) + expf(acc.w - m)) : 0.f;
#pragma unroll
    for (int o = 16; o > 0; o >>= 1) s += __shfl_xor_sync(0xffffffffu, s, o);
    float L = m + logf(s);

    if (active) {
        float4 o4;
        o4.x = acc.x - L; o4.y = acc.y - L;
        o4.z = acc.z - L; o4.w = acc.w - L;
        *(float4*)&out[(size_t)node * 40 + lane * 4] = o4;
    }
}

// ---------------- launch (gemm1 at index 3 so ncu profiles it) ----------------
extern "C" void kernel_launch(void* const* d_in, const int* in_sizes, int n_in,
                              void* d_out, int out_size) {
    const float* x  = (const float*)d_in[0];
    const int*   ei = (const int*)d_in[1];     // int32 (JAX x64 disabled)
    const float* W1 = (const float*)d_in[2];
    const float* b1 = (const float*)d_in[3];
    const float* W2 = (const float*)d_in[4];
    const float* b2 = (const float*)d_in[5];
    float* out = (float*)d_out;

    k_zero_deg<<<(NN + 255) / 256, 256>>>();
    k_hist<<<(EE + 255) / 256, 256>>>(ei);
    k_scan1<<<NBLK, SCAN_B>>>();

    k_gemm1<<<(NN + 127) / 128, 256>>>(x, W1);   // launch index 3 -> profiled

    k_scan2<<<1, 128>>>();
    k_scan3<<<(NN + 255) / 256, 256>>>();
    k_fill<<<(EE + 255) / 256, 256>>>(ei);

    k_agg1<<<(NN + 7) / 8, 256>>>(b1);

    k_gemm2<<<(NN + 127) / 128, 128>>>(W2);
    k_agg2<<<(NN + 7) / 8, 256>>>(b2, out);
}

// round 15
// speedup vs baseline: 1.1512x; 1.1512x over previous
#include <cuda_runtime.h>
#include <cuda_fp16.h>
#include <math.h>

#define NN 100000
#define EE 1600000
#define SCAN_B 1024
#define NBLK ((NN + SCAN_B - 1) / SCAN_B)   // 98

// ---------------- scratch (no allocations allowed) ----------------
__device__ __align__(16) float  g_dinv[NN];
__device__ __align__(16) int    g_degi[NN];
__device__ __align__(16) int    g_rowstart[NN + 1];
__device__ __align__(16) int    g_cursor[NN];
__device__ __align__(16) int    g_bsum[256];
__device__ __align__(16) int    g_bsum2[256];
__device__ __align__(16) int    g_esrc[EE];
__device__ __align__(16) __half g_xw_h[(size_t)NN * 128]; // x @ W1 (fp16)
__device__ __align__(16) float  g_h[(size_t)NN * 128];    // relu(agg layer1) fp32
__device__ __align__(16) __half g_hw2h[(size_t)NN * 40];  // h @ W2 (fp16)

// ---------------- degree histogram ----------------
__global__ void k_zero_deg() {
    int i = blockIdx.x * blockDim.x + threadIdx.x;
    if (i < NN) g_degi[i] = 0;
}

__global__ void k_hist(const int* __restrict__ ei) {
    int e = blockIdx.x * blockDim.x + threadIdx.x;
    if (e < EE) atomicAdd(&g_degi[ei[EE + e]], 1);
}

// ---------------- prefix scan (exclusive) of g_degi -> g_rowstart; fused dinv ----------------
__global__ void k_scan1() {
    __shared__ int sh[SCAN_B];
    int i = blockIdx.x * SCAN_B + threadIdx.x;
    int v = (i < NN) ? g_degi[i] : 0;
    if (i < NN) g_dinv[i] = rsqrtf((float)(v + 1));   // fused: deg + self loop
    sh[threadIdx.x] = v;
    __syncthreads();
    for (int o = 1; o < SCAN_B; o <<= 1) {
        int t = (threadIdx.x >= o) ? sh[threadIdx.x - o] : 0;
        __syncthreads();
        sh[threadIdx.x] += t;
        __syncthreads();
    }
    if (threadIdx.x == SCAN_B - 1) g_bsum[blockIdx.x] = sh[SCAN_B - 1];
    if (i < NN) g_rowstart[i] = sh[threadIdx.x] - v;   // exclusive
}

__global__ void k_scan2() {
    __shared__ int sh[128];
    int v = (threadIdx.x < NBLK) ? g_bsum[threadIdx.x] : 0;
    sh[threadIdx.x] = v;
    __syncthreads();
    for (int o = 1; o < 128; o <<= 1) {
        int t = (threadIdx.x >= o) ? sh[threadIdx.x - o] : 0;
        __syncthreads();
        sh[threadIdx.x] += t;
        __syncthreads();
    }
    g_bsum2[threadIdx.x] = sh[threadIdx.x] - v;        // exclusive
}

__global__ void k_scan3() {
    int i = blockIdx.x * blockDim.x + threadIdx.x;
    if (i < NN) {
        int r = g_rowstart[i] + g_bsum2[i / SCAN_B];
        g_rowstart[i] = r;
        g_cursor[i] = r;
    }
    if (i == 0) g_rowstart[NN] = EE;
}

// ---------------- counting-sort fill: CSR over dst ----------------
__global__ void k_fill(const int* __restrict__ ei) {
    int e = blockIdx.x * blockDim.x + threadIdx.x;
    if (e < EE) {
        int s = ei[e];
        int d = ei[EE + e];
        int pos = atomicAdd(&g_cursor[d], 1);
        g_esrc[pos] = s;
    }
}

// ---------------- mma + cp.async helpers ----------------
__device__ __forceinline__ void mma_tf32(float* d, const unsigned* a, const unsigned* b) {
    asm volatile(
        "mma.sync.aligned.m16n8k8.row.col.f32.tf32.tf32.f32 "
        "{%0,%1,%2,%3}, {%4,%5,%6,%7}, {%8,%9}, {%0,%1,%2,%3};"
        : "+f"(d[0]), "+f"(d[1]), "+f"(d[2]), "+f"(d[3])
        : "r"(a[0]), "r"(a[1]), "r"(a[2]), "r"(a[3]),
          "r"(b[0]), "r"(b[1]));
}

__device__ __forceinline__ void cp16(void* dst, const void* src, int src_bytes) {
    unsigned d = (unsigned)__cvta_generic_to_shared(dst);
    asm volatile("cp.async.cg.shared.global [%0], [%1], 16, %2;"
                 :: "r"(d), "l"(src), "r"(src_bytes) : "memory");
}
__device__ __forceinline__ void cp_commit() { asm volatile("cp.async.commit_group;" ::: "memory"); }
__device__ __forceinline__ void cp_wait1()  { asm volatile("cp.async.wait_group 1;" ::: "memory"); }
__device__ __forceinline__ void cp_wait0()  { asm volatile("cp.async.wait_group 0;" ::: "memory"); }

// ---------------- GEMM1 (tf32, 2-stage cp.async — proven 75us config) ----------------
// g_xw_h = fp16( x[N,256] @ W1[256,128] ). 128x128 block, 8 warps (2Mx4N), BK=16.
__global__ void __launch_bounds__(256) k_gemm1(const float* __restrict__ A,
                                               const float* __restrict__ B) {
    __shared__ float As[2][128][20];   // [m][k], stride 20 -> conflict-free frags
    __shared__ float Bs[2][16][132];   // [k][n]
    const int tid   = threadIdx.x;
    const int lane  = tid & 31;
    const int gid   = lane >> 2;    // 0..7
    const int tig   = lane & 3;     // 0..3
    const int warpM = (tid >> 5) & 1;
    const int warpN = (tid >> 6);   // 0..3
    const int blockRow = blockIdx.x * 128;

    float acc[4][4][4];
#pragma unroll
    for (int mt = 0; mt < 4; mt++)
#pragma unroll
        for (int nt = 0; nt < 4; nt++)
#pragma unroll
            for (int r = 0; r < 4; r++) acc[mt][nt][r] = 0.f;

    const int ar0 = tid >> 1, ak0 = (tid & 1) * 8;
    const int bk0 = tid >> 4, bn0 = (tid & 15) * 8;

    auto load_stage = [&](int st, int k0) {
        int row = blockRow + ar0;
        int ok  = (row < NN) ? 16 : 0;
        const float* src = &A[(size_t)row * 256 + k0 + ak0];
        cp16(&As[st][ar0][ak0],     src,     ok);
        cp16(&As[st][ar0][ak0 + 4], src + 4, ok);
        const float* bs = &B[(size_t)(k0 + bk0) * 128 + bn0];
        cp16(&Bs[st][bk0][bn0],     bs,     16);
        cp16(&Bs[st][bk0][bn0 + 4], bs + 4, 16);
        cp_commit();
    };

    load_stage(0, 0);

    for (int it = 0; it < 16; it++) {
        int st = it & 1;
        if (it + 1 < 16) {
            load_stage(st ^ 1, (it + 1) * 16);
            cp_wait1();
        } else {
            cp_wait0();
        }
        __syncthreads();

#pragma unroll
        for (int ks = 0; ks < 2; ks++) {
            int k = ks * 8 + tig;
            unsigned a[4][4], b[4][2];
#pragma unroll
            for (int mt = 0; mt < 4; mt++) {
                int r = warpM * 64 + mt * 16 + gid;
                a[mt][0] = __float_as_uint(As[st][r][k]);
                a[mt][1] = __float_as_uint(As[st][r + 8][k]);
                a[mt][2] = __float_as_uint(As[st][r][k + 4]);
                a[mt][3] = __float_as_uint(As[st][r + 8][k + 4]);
            }
#pragma unroll
            for (int nt = 0; nt < 4; nt++) {
                int c = warpN * 32 + nt * 8 + gid;
                b[nt][0] = __float_as_uint(Bs[st][k][c]);
                b[nt][1] = __float_as_uint(Bs[st][k + 4][c]);
            }
#pragma unroll
            for (int mt = 0; mt < 4; mt++)
#pragma unroll
                for (int nt = 0; nt < 4; nt++)
                    mma_tf32(acc[mt][nt], a[mt], b[nt]);
        }
        __syncthreads();
    }

#pragma unroll
    for (int mt = 0; mt < 4; mt++) {
        int r0 = blockRow + warpM * 64 + mt * 16 + gid;
#pragma unroll
        for (int nt = 0; nt < 4; nt++) {
            int c = warpN * 32 + nt * 8 + tig * 2;
            if (r0 < NN)
                *(__half2*)&g_xw_h[(size_t)r0 * 128 + c] =
                    __floats2half2_rn(acc[mt][nt][0], acc[mt][nt][1]);
            if (r0 + 8 < NN)
                *(__half2*)&g_xw_h[(size_t)(r0 + 8) * 128 + c] =
                    __floats2half2_rn(acc[mt][nt][2], acc[mt][nt][3]);
        }
    }
}

// ---------------- aggregation layer 1: warp per node, fp16 gather, 2-edge ILP ----------------
__global__ void __launch_bounds__(256) k_agg1(const float* __restrict__ b1) {
    int node = blockIdx.x * 8 + (threadIdx.x >> 5);
    int lane = threadIdx.x & 31;
    if (node >= NN) return;
    int beg = g_rowstart[node];
    int end = g_rowstart[node + 1];
    float dd = g_dinv[node];

    float4 acc = make_float4(0.f, 0.f, 0.f, 0.f);
    int i = beg;
    for (; i + 1 < end; i += 2) {
        int s0 = g_esrc[i];
        int s1 = g_esrc[i + 1];
        float n0 = dd * g_dinv[s0];
        float n1 = dd * g_dinv[s1];
        __half2 p0[2], p1[2];
        *(uint2*)p0 = *(const uint2*)&g_xw_h[(size_t)s0 * 128 + lane * 4];
        *(uint2*)p1 = *(const uint2*)&g_xw_h[(size_t)s1 * 128 + lane * 4];
        float2 a0 = __half22float2(p0[0]), a1 = __half22float2(p0[1]);
        float2 c0 = __half22float2(p1[0]), c1 = __half22float2(p1[1]);
        acc.x += a0.x * n0 + c0.x * n1;
        acc.y += a0.y * n0 + c0.y * n1;
        acc.z += a1.x * n0 + c1.x * n1;
        acc.w += a1.y * n0 + c1.y * n1;
    }
    if (i < end) {
        int s = g_esrc[i];
        float nrm = dd * g_dinv[s];
        __half2 p[2];
        *(uint2*)p = *(const uint2*)&g_xw_h[(size_t)s * 128 + lane * 4];
        float2 f0 = __half22float2(p[0]);
        float2 f1 = __half22float2(p[1]);
        acc.x += f0.x * nrm; acc.y += f0.y * nrm;
        acc.z += f1.x * nrm; acc.w += f1.y * nrm;
    }
    float self = dd * dd;
    __half2 sp[2];
    *(uint2*)sp = *(const uint2*)&g_xw_h[(size_t)node * 128 + lane * 4];
    float2 s0 = __half22float2(sp[0]);
    float2 s1 = __half22float2(sp[1]);
    float4 bb = *(const float4*)&b1[lane * 4];
    acc.x = fmaxf(acc.x + s0.x * self + bb.x, 0.f);
    acc.y = fmaxf(acc.y + s0.y * self + bb.y, 0.f);
    acc.z = fmaxf(acc.z + s1.x * self + bb.z, 0.f);
    acc.w = fmaxf(acc.w + s1.y * self + bb.w, 0.f);
    *(float4*)&g_h[(size_t)node * 128 + lane * 4] = acc;
}

// ---------------- GEMM2 (tf32 MMA, double-buffered; fp16 epilogue) ----------------
// 128-row block, 4 warps, warp tile 32x40 (2 x m16, 5 x n8), BK=32.
__global__ void __launch_bounds__(128) k_gemm2(const float* __restrict__ B) {
    __shared__ float As[2][128][36];   // [m][k] pad 4
    __shared__ float Bs[2][32][40];    // [k][n]
    const int tid  = threadIdx.x;
    const int lane = tid & 31;
    const int gid  = lane >> 2;
    const int tig  = lane & 3;
    const int warp = tid >> 5;         // 0..3
    const int blockRow = blockIdx.x * 128;

    float acc[2][5][4];
#pragma unroll
    for (int mt = 0; mt < 2; mt++)
#pragma unroll
        for (int nt = 0; nt < 5; nt++)
#pragma unroll
            for (int r = 0; r < 4; r++) acc[mt][nt][r] = 0.f;

    auto load_stage = [&](int st, int k0) {
        int row = blockRow + tid;
        int ok  = (row < NN) ? 16 : 0;
        const float* src = &g_h[(size_t)row * 128 + k0];
#pragma unroll
        for (int c = 0; c < 8; c++)
            cp16(&As[st][tid][c * 4], src + c * 4, ok);
#pragma unroll
        for (int idx = tid; idx < 320; idx += 128) {
            int kk = idx / 10;
            int c4 = (idx % 10) * 4;
            cp16(&Bs[st][kk][c4], &B[(size_t)(k0 + kk) * 40 + c4], 16);
        }
        cp_commit();
    };

    load_stage(0, 0);

    for (int it = 0; it < 4; it++) {
        int st = it & 1;
        if (it + 1 < 4) {
            load_stage(st ^ 1, (it + 1) * 32);
            cp_wait1();
        } else {
            cp_wait0();
        }
        __syncthreads();

#pragma unroll
        for (int ks = 0; ks < 4; ks++) {
            int k = ks * 8 + tig;
            unsigned a[2][4], b[5][2];
#pragma unroll
            for (int mt = 0; mt < 2; mt++) {
                int r = warp * 32 + mt * 16 + gid;
                a[mt][0] = __float_as_uint(As[st][r][k]);
                a[mt][1] = __float_as_uint(As[st][r + 8][k]);
                a[mt][2] = __float_as_uint(As[st][r][k + 4]);
                a[mt][3] = __float_as_uint(As[st][r + 8][k + 4]);
            }
#pragma unroll
            for (int nt = 0; nt < 5; nt++) {
                int c = nt * 8 + gid;
                b[nt][0] = __float_as_uint(Bs[st][k][c]);
                b[nt][1] = __float_as_uint(Bs[st][k + 4][c]);
            }
#pragma unroll
            for (int mt = 0; mt < 2; mt++)
#pragma unroll
                for (int nt = 0; nt < 5; nt++)
                    mma_tf32(acc[mt][nt], a[mt], b[nt]);
        }
        __syncthreads();
    }

#pragma unroll
    for (int mt = 0; mt < 2; mt++) {
        int r0 = blockRow + warp * 32 + mt * 16 + gid;
#pragma unroll
        for (int nt = 0; nt < 5; nt++) {
            int c = nt * 8 + tig * 2;
            if (r0 < NN)
                *(__half2*)&g_hw2h[(size_t)r0 * 40 + c] =
                    __floats2half2_rn(acc[mt][nt][0], acc[mt][nt][1]);
            if (r0 + 8 < NN)
                *(__half2*)&g_hw2h[(size_t)(r0 + 8) * 40 + c] =
                    __floats2half2_rn(acc[mt][nt][2], acc[mt][nt][3]);
        }
    }
}

// ---------------- aggregation layer 2 + bias + log_softmax, warp per node, fp16 gather ----------------
__global__ void __launch_bounds__(256) k_agg2(const float* __restrict__ b2,
                                              float* __restrict__ out) {
    int node = blockIdx.x * 8 + (threadIdx.x >> 5);
    int lane = threadIdx.x & 31;
    if (node >= NN) return;
    int beg = g_rowstart[node];
    int end = g_rowstart[node + 1];
    float dd = g_dinv[node];
    bool active = lane < 10;   // 10 x 4 halves cover 40 cols

    float4 acc = make_float4(0.f, 0.f, 0.f, 0.f);
    for (int i = beg; i < end; i++) {
        int s = g_esrc[i];
        float nrm = dd * g_dinv[s];
        if (active) {
            __half2 p[2];
            *(uint2*)p = *(const uint2*)&g_hw2h[(size_t)s * 40 + lane * 4];
            float2 f0 = __half22float2(p[0]);
            float2 f1 = __half22float2(p[1]);
            acc.x += f0.x * nrm; acc.y += f0.y * nrm;
            acc.z += f1.x * nrm; acc.w += f1.y * nrm;
        }
    }
    if (active) {
        float self = dd * dd;
        __half2 sp[2];
        *(uint2*)sp = *(const uint2*)&g_hw2h[(size_t)node * 40 + lane * 4];
        float2 s0 = __half22float2(sp[0]);
        float2 s1 = __half22float2(sp[1]);
        float4 bb = *(const float4*)&b2[lane * 4];
        acc.x += s0.x * self + bb.x;
        acc.y += s0.y * self + bb.y;
        acc.z += s1.x * self + bb.z;
        acc.w += s1.y * self + bb.w;
    }

    float m = active ? fmaxf(fmaxf(acc.x, acc.y), fmaxf(acc.z, acc.w)) : -INFINITY;
#pragma unroll
    for (int o = 16; o > 0; o >>= 1) m = fmaxf(m, __shfl_xor_sync(0xffffffffu, m, o));
    float s = active ? (expf(acc.x - m) + expf(acc.y - m) +
                        expf(acc.z - m) + expf(acc.w - m)) : 0.f;
#pragma unroll
    for (int o = 16; o > 0; o >>= 1) s += __shfl_xor_sync(0xffffffffu, s, o);
    float L = m + logf(s);

    if (active) {
        float4 o4;
        o4.x = acc.x - L; o4.y = acc.y - L;
        o4.z = acc.z - L; o4.w = acc.w - L;
        *(float4*)&out[(size_t)node * 40 + lane * 4] = o4;
    }
}

// ---------------- launch: fork CSR chain onto side stream, overlap with gemm1 ----------------
extern "C" void kernel_launch(void* const* d_in, const int* in_sizes, int n_in,
                              void* d_out, int out_size) {
    const float* x  = (const float*)d_in[0];
    const int*   ei = (const int*)d_in[1];     // int32 (JAX x64 disabled)
    const float* W1 = (const float*)d_in[2];
    const float* b1 = (const float*)d_in[3];
    const float* W2 = (const float*)d_in[4];
    const float* b2 = (const float*)d_in[5];
    float* out = (float*)d_out;

    // Host-side objects only (no device memory). Leaked intentionally —
    // kernel_launch is called a handful of times; streams must outlive capture.
    cudaStream_t s2;
    cudaStreamCreateWithFlags(&s2, cudaStreamNonBlocking);
    cudaEvent_t evFork, evJoin;
    cudaEventCreateWithFlags(&evFork, cudaEventDisableTiming);
    cudaEventCreateWithFlags(&evJoin, cudaEventDisableTiming);

    // fork: CSR build chain on s2 (independent of gemm1)
    cudaEventRecord(evFork, 0);
    cudaStreamWaitEvent(s2, evFork, 0);

    k_zero_deg<<<(NN + 255) / 256, 256, 0, s2>>>();
    k_hist<<<(EE + 255) / 256, 256, 0, s2>>>(ei);
    k_scan1<<<NBLK, SCAN_B, 0, s2>>>();
    k_scan2<<<1, 128, 0, s2>>>();
    k_scan3<<<(NN + 255) / 256, 256, 0, s2>>>();
    k_fill<<<(EE + 255) / 256, 256, 0, s2>>>(ei);
    cudaEventRecord(evJoin, s2);

    // main stream: dense GEMM1 runs concurrently with the CSR chain
    k_gemm1<<<(NN + 127) / 128, 256>>>(x, W1);

    // join: aggregation needs both gemm1 output and the CSR
    cudaStreamWaitEvent(0, evJoin, 0);

    k_agg1<<<(NN + 7) / 8, 256>>>(b1);
    k_gemm2<<<(NN + 127) / 128, 128>>>(W2);
    k_agg2<<<(NN + 7) / 8, 256>>>(b2, out);
}

// round 16
// speedup vs baseline: 1.1666x; 1.0134x over previous
#include <cuda_runtime.h>
#include <cuda_fp16.h>
#include <math.h>

#define NN 100000
#define EE 1600000
#define SCAN_B 1024
#define NBLK ((NN + SCAN_B - 1) / SCAN_B)   // 98

// ---------------- scratch (no allocations allowed) ----------------
__device__ __align__(16) float  g_dinv[NN];
__device__ __align__(16) int    g_degi[NN];
__device__ __align__(16) int    g_rowstart[NN + 1];
__device__ __align__(16) int    g_cursor[NN];
__device__ __align__(16) int    g_bsum[256];
__device__ __align__(16) int    g_bsum2[256];
__device__ __align__(16) int    g_esrc[EE];
__device__ __align__(16) __half g_xw_h[(size_t)NN * 128]; // x @ W1 (fp16)
__device__ __align__(16) float  g_h[(size_t)NN * 128];    // relu(agg layer1) fp32
__device__ __align__(16) __half g_hw2h[(size_t)NN * 40];  // h @ W2 (fp16)

// ---------------- degree histogram ----------------
__global__ void k_zero_deg() {
    int i = blockIdx.x * blockDim.x + threadIdx.x;
    if (i < NN) g_degi[i] = 0;
}

__global__ void k_hist(const int* __restrict__ ei) {
    int e = blockIdx.x * blockDim.x + threadIdx.x;
    if (e < EE) atomicAdd(&g_degi[ei[EE + e]], 1);
}

// ---------------- prefix scan (exclusive) of g_degi -> g_rowstart; fused dinv ----------------
__global__ void k_scan1() {
    __shared__ int sh[SCAN_B];
    int i = blockIdx.x * SCAN_B + threadIdx.x;
    int v = (i < NN) ? g_degi[i] : 0;
    if (i < NN) g_dinv[i] = rsqrtf((float)(v + 1));   // fused: deg + self loop
    sh[threadIdx.x] = v;
    __syncthreads();
    for (int o = 1; o < SCAN_B; o <<= 1) {
        int t = (threadIdx.x >= o) ? sh[threadIdx.x - o] : 0;
        __syncthreads();
        sh[threadIdx.x] += t;
        __syncthreads();
    }
    if (threadIdx.x == SCAN_B - 1) g_bsum[blockIdx.x] = sh[SCAN_B - 1];
    if (i < NN) g_rowstart[i] = sh[threadIdx.x] - v;   // exclusive
}

__global__ void k_scan2() {
    __shared__ int sh[128];
    int v = (threadIdx.x < NBLK) ? g_bsum[threadIdx.x] : 0;
    sh[threadIdx.x] = v;
    __syncthreads();
    for (int o = 1; o < 128; o <<= 1) {
        int t = (threadIdx.x >= o) ? sh[threadIdx.x - o] : 0;
        __syncthreads();
        sh[threadIdx.x] += t;
        __syncthreads();
    }
    g_bsum2[threadIdx.x] = sh[threadIdx.x] - v;        // exclusive
}

__global__ void k_scan3() {
    int i = blockIdx.x * blockDim.x + threadIdx.x;
    if (i < NN) {
        int r = g_rowstart[i] + g_bsum2[i / SCAN_B];
        g_rowstart[i] = r;
        g_cursor[i] = r;
    }
    if (i == 0) g_rowstart[NN] = EE;
}

// ---------------- counting-sort fill: CSR over dst ----------------
__global__ void k_fill(const int* __restrict__ ei) {
    int e = blockIdx.x * blockDim.x + threadIdx.x;
    if (e < EE) {
        int s = ei[e];
        int d = ei[EE + e];
        int pos = atomicAdd(&g_cursor[d], 1);
        g_esrc[pos] = s;
    }
}

// ---------------- mma + cp.async helpers ----------------
__device__ __forceinline__ void mma_tf32(float* d, const unsigned* a, const unsigned* b) {
    asm volatile(
        "mma.sync.aligned.m16n8k8.row.col.f32.tf32.tf32.f32 "
        "{%0,%1,%2,%3}, {%4,%5,%6,%7}, {%8,%9}, {%0,%1,%2,%3};"
        : "+f"(d[0]), "+f"(d[1]), "+f"(d[2]), "+f"(d[3])
        : "r"(a[0]), "r"(a[1]), "r"(a[2]), "r"(a[3]),
          "r"(b[0]), "r"(b[1]));
}

__device__ __forceinline__ void cp16(void* dst, const void* src, int src_bytes) {
    unsigned d = (unsigned)__cvta_generic_to_shared(dst);
    asm volatile("cp.async.cg.shared.global [%0], [%1], 16, %2;"
                 :: "r"(d), "l"(src), "r"(src_bytes) : "memory");
}
__device__ __forceinline__ void cp_commit() { asm volatile("cp.async.commit_group;" ::: "memory"); }
__device__ __forceinline__ void cp_wait1()  { asm volatile("cp.async.wait_group 1;" ::: "memory"); }
__device__ __forceinline__ void cp_wait0()  { asm volatile("cp.async.wait_group 0;" ::: "memory"); }

// ---------------- GEMM1 (tf32, 2-stage cp.async — proven 75us config) ----------------
// g_xw_h = fp16( x[N,256] @ W1[256,128] ). 128x128 block, 8 warps (2Mx4N), BK=16.
__global__ void __launch_bounds__(256) k_gemm1(const float* __restrict__ A,
                                               const float* __restrict__ B) {
    __shared__ float As[2][128][20];   // [m][k], stride 20 -> conflict-free frags
    __shared__ float Bs[2][16][132];   // [k][n]
    const int tid   = threadIdx.x;
    const int lane  = tid & 31;
    const int gid   = lane >> 2;    // 0..7
    const int tig   = lane & 3;     // 0..3
    const int warpM = (tid >> 5) & 1;
    const int warpN = (tid >> 6);   // 0..3
    const int blockRow = blockIdx.x * 128;

    float acc[4][4][4];
#pragma unroll
    for (int mt = 0; mt < 4; mt++)
#pragma unroll
        for (int nt = 0; nt < 4; nt++)
#pragma unroll
            for (int r = 0; r < 4; r++) acc[mt][nt][r] = 0.f;

    const int ar0 = tid >> 1, ak0 = (tid & 1) * 8;
    const int bk0 = tid >> 4, bn0 = (tid & 15) * 8;

    auto load_stage = [&](int st, int k0) {
        int row = blockRow + ar0;
        int ok  = (row < NN) ? 16 : 0;
        const float* src = &A[(size_t)row * 256 + k0 + ak0];
        cp16(&As[st][ar0][ak0],     src,     ok);
        cp16(&As[st][ar0][ak0 + 4], src + 4, ok);
        const float* bs = &B[(size_t)(k0 + bk0) * 128 + bn0];
        cp16(&Bs[st][bk0][bn0],     bs,     16);
        cp16(&Bs[st][bk0][bn0 + 4], bs + 4, 16);
        cp_commit();
    };

    load_stage(0, 0);

    for (int it = 0; it < 16; it++) {
        int st = it & 1;
        if (it + 1 < 16) {
            load_stage(st ^ 1, (it + 1) * 16);
            cp_wait1();
        } else {
            cp_wait0();
        }
        __syncthreads();

#pragma unroll
        for (int ks = 0; ks < 2; ks++) {
            int k = ks * 8 + tig;
            unsigned a[4][4], b[4][2];
#pragma unroll
            for (int mt = 0; mt < 4; mt++) {
                int r = warpM * 64 + mt * 16 + gid;
                a[mt][0] = __float_as_uint(As[st][r][k]);
                a[mt][1] = __float_as_uint(As[st][r + 8][k]);
                a[mt][2] = __float_as_uint(As[st][r][k + 4]);
                a[mt][3] = __float_as_uint(As[st][r + 8][k + 4]);
            }
#pragma unroll
            for (int nt = 0; nt < 4; nt++) {
                int c = warpN * 32 + nt * 8 + gid;
                b[nt][0] = __float_as_uint(Bs[st][k][c]);
                b[nt][1] = __float_as_uint(Bs[st][k + 4][c]);
            }
#pragma unroll
            for (int mt = 0; mt < 4; mt++)
#pragma unroll
                for (int nt = 0; nt < 4; nt++)
                    mma_tf32(acc[mt][nt], a[mt], b[nt]);
        }
        __syncthreads();
    }

#pragma unroll
    for (int mt = 0; mt < 4; mt++) {
        int r0 = blockRow + warpM * 64 + mt * 16 + gid;
#pragma unroll
        for (int nt = 0; nt < 4; nt++) {
            int c = warpN * 32 + nt * 8 + tig * 2;
            if (r0 < NN)
                *(__half2*)&g_xw_h[(size_t)r0 * 128 + c] =
                    __floats2half2_rn(acc[mt][nt][0], acc[mt][nt][1]);
            if (r0 + 8 < NN)
                *(__half2*)&g_xw_h[(size_t)(r0 + 8) * 128 + c] =
                    __floats2half2_rn(acc[mt][nt][2], acc[mt][nt][3]);
        }
    }
}

// ---------------- aggregation layer 1: warp per node, half-warps on even/odd edges ----------------
// Each half-warp (16 lanes x uint4 = 256B) gathers one full fp16 row per edge.
__global__ void __launch_bounds__(256) k_agg1(const float* __restrict__ b1) {
    int node = blockIdx.x * 8 + (threadIdx.x >> 5);
    int lane = threadIdx.x & 31;
    if (node >= NN) return;
    const int half = lane >> 4;     // 0: even-index edges, 1: odd
    const int hl   = lane & 15;     // 16-byte chunk id within the 256B row
    int beg = g_rowstart[node];
    int end = g_rowstart[node + 1];
    float dd = g_dinv[node];

    float acc[8];
#pragma unroll
    for (int j = 0; j < 8; j++) acc[j] = 0.f;

    for (int i = beg + half; i < end; i += 2) {
        int s = g_esrc[i];                      // broadcast within half-warp
        float nrm = dd * g_dinv[s];
        uint4 p = *(const uint4*)&g_xw_h[(size_t)s * 128 + hl * 8];
        const __half2* ph = (const __half2*)&p;
#pragma unroll
        for (int j = 0; j < 4; j++) {
            float2 f = __half22float2(ph[j]);
            acc[2 * j]     += f.x * nrm;
            acc[2 * j + 1] += f.y * nrm;
        }
    }

    // combine odd-half into even-half (lanes 0..15 get lane+16's partials)
#pragma unroll
    for (int j = 0; j < 8; j++)
        acc[j] += __shfl_down_sync(0xffffffffu, acc[j], 16);

    if (half == 0) {
        float self = dd * dd;
        uint4 sp = *(const uint4*)&g_xw_h[(size_t)node * 128 + hl * 8];
        const __half2* sph = (const __half2*)&sp;
        float2 f0 = __half22float2(sph[0]);
        float2 f1 = __half22float2(sph[1]);
        float2 f2 = __half22float2(sph[2]);
        float2 f3 = __half22float2(sph[3]);
        float4 bb0 = *(const float4*)&b1[hl * 8];
        float4 bb1 = *(const float4*)&b1[hl * 8 + 4];
        float4 o0, o1;
        o0.x = fmaxf(acc[0] + f0.x * self + bb0.x, 0.f);
        o0.y = fmaxf(acc[1] + f0.y * self + bb0.y, 0.f);
        o0.z = fmaxf(acc[2] + f1.x * self + bb0.z, 0.f);
        o0.w = fmaxf(acc[3] + f1.y * self + bb0.w, 0.f);
        o1.x = fmaxf(acc[4] + f2.x * self + bb1.x, 0.f);
        o1.y = fmaxf(acc[5] + f2.y * self + bb1.y, 0.f);
        o1.z = fmaxf(acc[6] + f3.x * self + bb1.z, 0.f);
        o1.w = fmaxf(acc[7] + f3.y * self + bb1.w, 0.f);
        *(float4*)&g_h[(size_t)node * 128 + hl * 8]     = o0;
        *(float4*)&g_h[(size_t)node * 128 + hl * 8 + 4] = o1;
    }
}

// ---------------- GEMM2 (tf32 MMA, double-buffered; fp16 epilogue) ----------------
// 128-row block, 4 warps, warp tile 32x40 (2 x m16, 5 x n8), BK=32.
__global__ void __launch_bounds__(128) k_gemm2(const float* __restrict__ B) {
    __shared__ float As[2][128][36];   // [m][k] pad 4
    __shared__ float Bs[2][32][40];    // [k][n]
    const int tid  = threadIdx.x;
    const int lane = tid & 31;
    const int gid  = lane >> 2;
    const int tig  = lane & 3;
    const int warp = tid >> 5;         // 0..3
    const int blockRow = blockIdx.x * 128;

    float acc[2][5][4];
#pragma unroll
    for (int mt = 0; mt < 2; mt++)
#pragma unroll
        for (int nt = 0; nt < 5; nt++)
#pragma unroll
            for (int r = 0; r < 4; r++) acc[mt][nt][r] = 0.f;

    auto load_stage = [&](int st, int k0) {
        int row = blockRow + tid;
        int ok  = (row < NN) ? 16 : 0;
        const float* src = &g_h[(size_t)row * 128 + k0];
#pragma unroll
        for (int c = 0; c < 8; c++)
            cp16(&As[st][tid][c * 4], src + c * 4, ok);
#pragma unroll
        for (int idx = tid; idx < 320; idx += 128) {
            int kk = idx / 10;
            int c4 = (idx % 10) * 4;
            cp16(&Bs[st][kk][c4], &B[(size_t)(k0 + kk) * 40 + c4], 16);
        }
        cp_commit();
    };

    load_stage(0, 0);

    for (int it = 0; it < 4; it++) {
        int st = it & 1;
        if (it + 1 < 4) {
            load_stage(st ^ 1, (it + 1) * 32);
            cp_wait1();
        } else {
            cp_wait0();
        }
        __syncthreads();

#pragma unroll
        for (int ks = 0; ks < 4; ks++) {
            int k = ks * 8 + tig;
            unsigned a[2][4], b[5][2];
#pragma unroll
            for (int mt = 0; mt < 2; mt++) {
                int r = warp * 32 + mt * 16 + gid;
                a[mt][0] = __float_as_uint(As[st][r][k]);
                a[mt][1] = __float_as_uint(As[st][r + 8][k]);
                a[mt][2] = __float_as_uint(As[st][r][k + 4]);
                a[mt][3] = __float_as_uint(As[st][r + 8][k + 4]);
            }
#pragma unroll
            for (int nt = 0; nt < 5; nt++) {
                int c = nt * 8 + gid;
                b[nt][0] = __float_as_uint(Bs[st][k][c]);
                b[nt][1] = __float_as_uint(Bs[st][k + 4][c]);
            }
#pragma unroll
            for (int mt = 0; mt < 2; mt++)
#pragma unroll
                for (int nt = 0; nt < 5; nt++)
                    mma_tf32(acc[mt][nt], a[mt], b[nt]);
        }
        __syncthreads();
    }

#pragma unroll
    for (int mt = 0; mt < 2; mt++) {
        int r0 = blockRow + warp * 32 + mt * 16 + gid;
#pragma unroll
        for (int nt = 0; nt < 5; nt++) {
            int c = nt * 8 + tig * 2;
            if (r0 < NN)
                *(__half2*)&g_hw2h[(size_t)r0 * 40 + c] =
                    __floats2half2_rn(acc[mt][nt][0], acc[mt][nt][1]);
            if (r0 + 8 < NN)
                *(__half2*)&g_hw2h[(size_t)(r0 + 8) * 40 + c] =
                    __floats2half2_rn(acc[mt][nt][2], acc[mt][nt][3]);
        }
    }
}

// ---------------- aggregation layer 2 + bias + log_softmax, warp per node, fp16 gather ----------------
__global__ void __launch_bounds__(256) k_agg2(const float* __restrict__ b2,
                                              float* __restrict__ out) {
    int node = blockIdx.x * 8 + (threadIdx.x >> 5);
    int lane = threadIdx.x & 31;
    if (node >= NN) return;
    int beg = g_rowstart[node];
    int end = g_rowstart[node + 1];
    float dd = g_dinv[node];
    bool active = lane < 10;   // 10 x 4 halves cover 40 cols

    float4 acc = make_float4(0.f, 0.f, 0.f, 0.f);
    for (int i = beg; i < end; i++) {
        int s = g_esrc[i];
        float nrm = dd * g_dinv[s];
        if (active) {
            __half2 p[2];
            *(uint2*)p = *(const uint2*)&g_hw2h[(size_t)s * 40 + lane * 4];
            float2 f0 = __half22float2(p[0]);
            float2 f1 = __half22float2(p[1]);
            acc.x += f0.x * nrm; acc.y += f0.y * nrm;
            acc.z += f1.x * nrm; acc.w += f1.y * nrm;
        }
    }
    if (active) {
        float self = dd * dd;
        __half2 sp[2];
        *(uint2*)sp = *(const uint2*)&g_hw2h[(size_t)node * 40 + lane * 4];
        float2 s0 = __half22float2(sp[0]);
        float2 s1 = __half22float2(sp[1]);
        float4 bb = *(const float4*)&b2[lane * 4];
        acc.x += s0.x * self + bb.x;
        acc.y += s0.y * self + bb.y;
        acc.z += s1.x * self + bb.z;
        acc.w += s1.y * self + bb.w;
    }

    float m = active ? fmaxf(fmaxf(acc.x, acc.y), fmaxf(acc.z, acc.w)) : -INFINITY;
#pragma unroll
    for (int o = 16; o > 0; o >>= 1) m = fmaxf(m, __shfl_xor_sync(0xffffffffu, m, o));
    float s = active ? (expf(acc.x - m) + expf(acc.y - m) +
                        expf(acc.z - m) + expf(acc.w - m)) : 0.f;
#pragma unroll
    for (int o = 16; o > 0; o >>= 1) s += __shfl_xor_sync(0xffffffffu, s, o);
    float L = m + logf(s);

    if (active) {
        float4 o4;
        o4.x = acc.x - L; o4.y = acc.y - L;
        o4.z = acc.z - L; o4.w = acc.w - L;
        *(float4*)&out[(size_t)node * 40 + lane * 4] = o4;
    }
}

// ---------------- launch: fork CSR chain onto side stream, overlap with gemm1 ----------------
extern "C" void kernel_launch(void* const* d_in, const int* in_sizes, int n_in,
                              void* d_out, int out_size) {
    const float* x  = (const float*)d_in[0];
    const int*   ei = (const int*)d_in[1];     // int32 (JAX x64 disabled)
    const float* W1 = (const float*)d_in[2];
    const float* b1 = (const float*)d_in[3];
    const float* W2 = (const float*)d_in[4];
    const float* b2 = (const float*)d_in[5];
    float* out = (float*)d_out;

    // Host-side objects only (no device memory). Leaked intentionally —
    // kernel_launch is called a handful of times; streams must outlive capture.
    cudaStream_t s2;
    cudaStreamCreateWithFlags(&s2, cudaStreamNonBlocking);
    cudaEvent_t evFork, evJoin;
    cudaEventCreateWithFlags(&evFork, cudaEventDisableTiming);
    cudaEventCreateWithFlags(&evJoin, cudaEventDisableTiming);

    // fork: CSR build chain on s2 (independent of gemm1)
    cudaEventRecord(evFork, 0);
    cudaStreamWaitEvent(s2, evFork, 0);

    k_zero_deg<<<(NN + 255) / 256, 256, 0, s2>>>();
    k_hist<<<(EE + 255) / 256, 256, 0, s2>>>(ei);
    k_scan1<<<NBLK, SCAN_B, 0, s2>>>();
    k_scan2<<<1, 128, 0, s2>>>();
    k_scan3<<<(NN + 255) / 256, 256, 0, s2>>>();
    k_fill<<<(EE + 255) / 256, 256, 0, s2>>>(ei);
    cudaEventRecord(evJoin, s2);

    // main stream: dense GEMM1 runs concurrently with the CSR chain
    k_gemm1<<<(NN + 127) / 128, 256>>>(x, W1);

    // join: aggregation needs both gemm1 output and the CSR
    cudaStreamWaitEvent(0, evJoin, 0);

    k_agg1<<<(NN + 7) / 8, 256>>>(b1);
    k_gemm2<<<(NN + 127) / 128, 128>>>(W2);
    k_agg2<<<(NN + 7) / 8, 256>>>(b2, out);
}